// round 15
// baseline (speedup 1.0000x reference)
#include <cuda_runtime.h>
#include <math.h>
#include <stdint.h>

// Problem constants
#define T_LEN 512
#define BATCH 64
#define HID   512
#define GATES 2048          // 4*H
#define L0_K  256
#define L1_K  1024
#define M_ROWS (BATCH * T_LEN)   // 32768

typedef unsigned long long u64;

// ---------------------------------------------------------------------------
// Packed f32x2 helpers (sm_100+; FFMA2 is only reachable via PTX)
// ---------------------------------------------------------------------------
__device__ __forceinline__ u64 dup2(float x) {
    u64 r; asm("mov.b64 %0, {%1, %1};" : "=l"(r) : "f"(x)); return r;
}
__device__ __forceinline__ void ffma2(u64& d, u64 a, u64 b) {
    asm("fma.rn.f32x2 %0, %1, %2, %0;" : "+l"(d) : "l"(a), "l"(b));
}
__device__ __forceinline__ u64 pack2(float lo, float hi) {
    u64 r; asm("mov.b64 %0, {%1, %2};" : "=l"(r) : "f"(lo), "f"(hi)); return r;
}
__device__ __forceinline__ float2 unpack2(u64 v) {
    float2 r; asm("mov.b64 {%0, %1}, %2;" : "=f"(r.x), "=f"(r.y) : "l"(v)); return r;
}

// cp.async: 16B global->shared, L2-direct (.cg). Per-thread commit groups.
__device__ __forceinline__ void cp_async16(void* smem_ptr, const void* gptr) {
    uint32_t s = (uint32_t)__cvta_generic_to_shared(smem_ptr);
    asm volatile("cp.async.cg.shared.global [%0], [%1], 16;" :: "r"(s), "l"(gptr));
}
__device__ __forceinline__ void cp_async_commit() {
    asm volatile("cp.async.commit_group;");
}
template <int N>
__device__ __forceinline__ void cp_async_wait() {
    asm volatile("cp.async.wait_group %0;" :: "n"(N) : "memory");
}

// Fast gates: MUFU ex2-based exp (2-ulp). Avoid tanh.approx (abs err ~9e-4:
// too close to the 1e-3 budget over a 512-step recurrence).
__device__ __forceinline__ float fsigmoid(float x) {
    return 1.0f / (1.0f + __expf(-x));
}
__device__ __forceinline__ float ftanh(float x) {
    return 2.0f / (1.0f + __expf(-2.0f * x)) - 1.0f;
}

// ---------------------------------------------------------------------------
// Scratch (static __device__ arrays; no allocation allowed in kernel_launch)
// Row key for pre0/pre1/out0 is (t*64 + b): recurrence step t reads/writes one
// CONTIGUOUS region, streamed sequentially over t.
// g_h is K-MAJOR [parity][dir][k][b]: per-step smem fill is a straight
// contiguous copy (cp.async pipeline, no transpose).
// ---------------------------------------------------------------------------
__device__ float g_pre0[(size_t)M_ROWS * 4096];   // rows t*64+b, cols dir*2048+gate*512+j
__device__ float g_pre1[(size_t)M_ROWS * 2048];   // rows t*64+b (L1 fwd)
__device__ float g_out0[(size_t)M_ROWS * 1024];   // rows t*64+b, cols dir*512+j
__device__ float g_h[2][2][HID][BATCH];           // [parity][dir][k][b]  (ping-pong h)
__device__ float g_hbwd1[BATCH][HID];             // layer-1 backward single-step h
__device__ int   g_bar;                           // persistent-kernel grid barrier counter

// ---------------------------------------------------------------------------
// Zero the recurrent state + barrier counter (runs before each persistent layer)
// ---------------------------------------------------------------------------
__global__ void zero_states_kernel() {
    int i = blockIdx.x * blockDim.x + threadIdx.x;
    if (i == 0) g_bar = 0;
    if (i < 2 * 2 * BATCH * HID) ((float*)g_h)[i] = 0.0f;
}

// ---------------------------------------------------------------------------
// Input-projection GEMM:  Y[perm(m)][n] = sum_k X[m][k]*W[n][k] + b1[n] + b2[n]
// Tile 128(M) x 128(N) x 16(K), 256 threads, 8x8 micro-tile, FFMA2 (m-pairs
// straight from LDS.128 register pairs; only W needs dup2).
// Register double-buffering: the NEXT k-tile's LDGs are issued before the
// current tile's compute, hiding their DRAM latency under the FFMA2 window.
// permute!=0 applies the bijection m -> (m%512)*64 + m/512, re-keying
// (b,t)-ordered input rows to (t,b)-ordered output rows for streaming reads.
// Requires M%128==0, N%128==0, K%16==0.
// ---------------------------------------------------------------------------
__global__ __launch_bounds__(256)
void gemm_bias_kernel(const float* __restrict__ X, const float* __restrict__ W,
                      const float* __restrict__ bias1, const float* __restrict__ bias2,
                      float* __restrict__ Y, int M, int N, int K, int permute)
{
    __shared__ float Xs[16][128];
    __shared__ float Ws[16][128];

    const int tid   = threadIdx.x;
    const int mBase = blockIdx.y * 128;
    const int nBase = blockIdx.x * 128;
    const int tm = tid >> 4;          // 0..15
    const int tn = tid & 15;          // 0..15
    const int m0 = tm * 8;
    const int n0 = tn * 8;

    u64 acc2[4][8];
#pragma unroll
    for (int i = 0; i < 4; i++)
#pragma unroll
        for (int j = 0; j < 8; j++) acc2[i][j] = 0ull;

    // per-thread tile-load coordinates (2 rows of X, 2 rows of W per thread)
    int lrr[2], lkq[2];
#pragma unroll
    for (int q = 0; q < 2; q++) {
        int idx = tid + q * 256;          // 0..511
        lrr[q] = idx & 127;               // row within tile
        lkq[q] = idx >> 7;                // 0..3 (float4 index along k)
    }

    // prefetch registers for the next k-tile
    float4 vx[2], vw[2];
#pragma unroll
    for (int q = 0; q < 2; q++) {
        vx[q] = *(const float4*)&X[(size_t)(mBase + lrr[q]) * K + 0 + lkq[q] * 4];
        vw[q] = *(const float4*)&W[(size_t)(nBase + lrr[q]) * K + 0 + lkq[q] * 4];
    }

    for (int kt = 0; kt < K; kt += 16) {
        // store the prefetched tile (smem free: previous compute fully consumed it)
#pragma unroll
        for (int q = 0; q < 2; q++) {
            int rr = lrr[q], kq = lkq[q];
            Xs[kq * 4 + 0][rr] = vx[q].x; Xs[kq * 4 + 1][rr] = vx[q].y;
            Xs[kq * 4 + 2][rr] = vx[q].z; Xs[kq * 4 + 3][rr] = vx[q].w;
            Ws[kq * 4 + 0][rr] = vw[q].x; Ws[kq * 4 + 1][rr] = vw[q].y;
            Ws[kq * 4 + 2][rr] = vw[q].z; Ws[kq * 4 + 3][rr] = vw[q].w;
        }
        __syncthreads();

        // issue next tile's LDGs now; they retire during the compute below
        if (kt + 16 < K) {
#pragma unroll
            for (int q = 0; q < 2; q++) {
                vx[q] = *(const float4*)&X[(size_t)(mBase + lrr[q]) * K + (kt + 16) + lkq[q] * 4];
                vw[q] = *(const float4*)&W[(size_t)(nBase + lrr[q]) * K + (kt + 16) + lkq[q] * 4];
            }
        }

#pragma unroll
        for (int kk = 0; kk < 16; kk++) {
            ulonglong2 a01 = *(const ulonglong2*)&Xs[kk][m0];
            ulonglong2 a23 = *(const ulonglong2*)&Xs[kk][m0 + 4];
            float4 b0 = *(const float4*)&Ws[kk][n0];
            float4 b1 = *(const float4*)&Ws[kk][n0 + 4];
            u64 A[4] = { a01.x, a01.y, a23.x, a23.y };
            u64 B[8] = { dup2(b0.x), dup2(b0.y), dup2(b0.z), dup2(b0.w),
                         dup2(b1.x), dup2(b1.y), dup2(b1.z), dup2(b1.w) };
#pragma unroll
            for (int i = 0; i < 4; i++)
#pragma unroll
                for (int j = 0; j < 8; j++) ffma2(acc2[i][j], A[i], B[j]);
        }
        __syncthreads();
    }

    // loop-invariant bias hoist (col depends on j only)
    float bsum[8];
#pragma unroll
    for (int j = 0; j < 8; j++) {
        int col = nBase + n0 + j;
        bsum[j] = bias1[col] + bias2[col];
    }

#pragma unroll
    for (int i = 0; i < 4; i++) {
        int mA = mBase + m0 + 2 * i;
        int mB = mA + 1;
        if (permute) {
            mA = (mA & (T_LEN - 1)) * BATCH + (mA >> 9);
            mB = (mB & (T_LEN - 1)) * BATCH + (mB >> 9);
        }
        size_t row0 = (size_t)mA * N;
        size_t row1 = (size_t)mB * N;
#pragma unroll
        for (int j = 0; j < 8; j++) {
            int col = nBase + n0 + j;
            float2 v = unpack2(acc2[i][j]);
            Y[row0 + col] = v.x + bsum[j];
            Y[row1 + col] = v.y + bsum[j];
        }
    }
}

// ---------------------------------------------------------------------------
// Persistent LSTM layer, templated on j-tile width JW (8 for L0 -> 128 blocks,
// 4 for L1 -> 128 blocks so the single-direction layer fills the chip).
// 128 threads/block; smem <= 205KB -> 1 CTA/SM -> grid <= 128 blocks is a
// single co-resident wave, so the software grid barrier is safe.
// w_hh slice stays in smem the whole layer; c stays in registers.
// h ping-pongs through gmem K-MAJOR; the per-step smem fill is a 4-chunk
// cp.async pipeline overlapped with the GEMM (chunks are disjoint h_s
// regions, so no double buffer). Correctness of the ping-pong across blocks:
// the per-step __threadfence() emits CCTL.IVALL (L1D invalidate), and
// cp.async.cg bypasses L1 anyway. Async reads of plane t&1 can never race
// writes (those target plane (t+1)&1), and all groups drain before the gates.
// Issue budget per k (JW=8, 1 warp/SMSP): 8 FFMA2 (16-cyc fma floor) +
// 4 dup2 + 2 LDS = 14 issues <= 16 slots. (A 256-thread variant would double
// the dup2s per SMSP -> 20 issues > 16 slots, issue-bound; 128 is optimal.)
// ---------------------------------------------------------------------------
template <int JW>
struct StepCfg {
    static const int NN   = 4 * JW;              // gate rows per block
    static const int SMEM = (512 * 64 + 512 * NN + NN * 65) * 4;
    static const int NCOL = NN / 8;              // micro-tile cols per thread (4 or 2)
};

#define KCHUNK 128                               // k per pipeline chunk (4 chunks)

__device__ __forceinline__ int ld_acquire_gpu(const int* p) {
    int v;
    asm volatile("ld.acquire.gpu.global.s32 %0, [%1];" : "=r"(v) : "l"(p) : "memory");
    return v;
}

template <int JW>
__global__ __launch_bounds__(128)
void lstm_layer_persistent_kernel(const float* __restrict__ pre, int preN,
                                  const float* __restrict__ whh,   // rows: dir*2048+gate*512+j
                                  float* __restrict__ hbuf,        // g_h base [2][2][HID][BATCH]
                                  float* __restrict__ outp)        // rows t*64+b, or nullptr
{
    const int NN   = StepCfg<JW>::NN;
    const int NCOL = StepCfg<JW>::NCOL;

    extern __shared__ float sm[];
    float* h_s = sm;                        // [k][b]  512 x 64
    float* w_s = sm + 512 * 64;             // [k][nn] 512 x NN
    float* g_s = w_s + 512 * NN;            // [nn][b] NN x 65 (padded)

    const int tid   = threadIdx.x;
    const int dir   = blockIdx.y;
    const int jbase = blockIdx.x * JW;
    const int nb    = gridDim.x * gridDim.y;
    const int HPAR  = 2 * BATCH * HID;      // floats per parity plane

    // ---- load w_hh slice ONCE (NN rows x 512 k), transposed to k-major ----
    {
        int nn = tid % NN;
        int kg = tid / NN;                  // 0..(128/NN - 1)
        int gate = nn / JW, jj = nn % JW;
        const float4* wsrc =
            (const float4*)(whh + (size_t)(dir * GATES + gate * HID + jbase + jj) * HID);
#pragma unroll 4
        for (int kq = kg * NN; kq < kg * NN + NN; kq++) {  // 128 float4s over 128/NN groups
            float4 v = wsrc[kq];
            int k = kq * 4;
            w_s[(k + 0) * NN + nn] = v.x;
            w_s[(k + 1) * NN + nn] = v.y;
            w_s[(k + 2) * NN + nn] = v.z;
            w_s[(k + 3) * NN + nn] = v.w;
        }
    }

    // micro-tile mapping (constant over time): 4 batches x NCOL cols per thread
    const int tm = tid >> 3;            // 0..15
    const int tn = tid & 7;             // 0..7
    const int m0 = tm * 4;              // batch base
    const int n0 = tn * NCOL;           // nn base (stays within one gate)
    const int gate0 = n0 / JW;
    const int jq    = n0 % JW;

    // register-resident cell state for this thread's (b,jj) pairs
    const int NR = 64 * JW / 128;       // elementwise iterations (4 or 2)
    float c_reg[NR > 0 ? NR : 1];
#pragma unroll
    for (int r = 0; r < NR; r++) c_reg[r] = 0.0f;

    const int colOff = dir * GATES + gate0 * HID + jbase + jq;

    // prefetch registers for the pre-activation gate inputs (row key t*64+b)
    float4 pf0[2], pf1[2];
    auto prefetch_pre = [&](int tt) {
        int time2 = dir ? (T_LEN - 1 - tt) : tt;
#pragma unroll
        for (int p = 0; p < 2; p++) {
            size_t r0 = (size_t)(time2 * BATCH + m0 + 2 * p) * preN + colOff;
            size_t r1 = r0 + preN;
            if (NCOL == 4) {
                pf0[p] = *(const float4*)&pre[r0];
                pf1[p] = *(const float4*)&pre[r1];
            } else {
                float2 a = *(const float2*)&pre[r0];
                float2 b = *(const float2*)&pre[r1];
                pf0[p].x = a.x; pf0[p].y = a.y;
                pf1[p].x = b.x; pf1[p].y = b.y;
            }
        }
    };

    prefetch_pre(0);

    for (int t = 0; t < T_LEN; t++) {
        const float* hprev = hbuf + (size_t)(t & 1) * HPAR;
        float*       hnext = hbuf + (size_t)((t + 1) & 1) * HPAR;
        const int time = dir ? (T_LEN - 1 - t) : t;

        // ---- accumulators from the prefetched input gates ----
        u64 acc2[2][NCOL];
#pragma unroll
        for (int p = 0; p < 2; p++) {
            acc2[p][0] = pack2(pf0[p].x, pf1[p].x);
            acc2[p][1] = pack2(pf0[p].y, pf1[p].y);
            if (NCOL == 4) {
                acc2[p][2]        = pack2(pf0[p].z, pf1[p].z);
                acc2[p][NCOL - 1] = pack2(pf0[p].w, pf1[p].w);
            }
        }

        // ---- cp.async chunk copier: k range [c*KCHUNK, (c+1)*KCHUNK) ----
        const float* hplane = hprev + (size_t)dir * HID * BATCH;
        auto copy_chunk = [&](int c) {
            const float4* src = (const float4*)(hplane + c * KCHUNK * BATCH);
            float4*       dst = (float4*)(h_s + c * KCHUNK * BATCH);
            // KCHUNK*64 floats = 2048 float4 per chunk; 16 per thread
#pragma unroll
            for (int i = 0; i < (KCHUNK * BATCH / 4) / 128; i++)
                cp_async16(dst + tid + i * 128, src + tid + i * 128);
            cp_async_commit();
        };

        copy_chunk(0);

        // ---- pipelined GEMM over 4 chunks: copy c+1 while computing c ----
#pragma unroll
        for (int c = 0; c < HID / KCHUNK; c++) {
            if (c + 1 < HID / KCHUNK) {
                copy_chunk(c + 1);
                cp_async_wait<1>();      // chunk c landed (c+1 may be in flight)
            } else {
                cp_async_wait<0>();      // last chunk: drain all
            }
            __syncthreads();             // cross-thread visibility of chunk c
                                         // (t=0,c=0 also guards w_s)

#pragma unroll 4
            for (int k = c * KCHUNK; k < (c + 1) * KCHUNK; k++) {
                ulonglong2 a = *(const ulonglong2*)&h_s[k * 64 + m0];
                if (NCOL == 4) {
                    float4 w4 = *(const float4*)&w_s[k * NN + n0];
                    u64 B0 = dup2(w4.x), B1 = dup2(w4.y), B2 = dup2(w4.z), B3 = dup2(w4.w);
                    ffma2(acc2[0][0], a.x, B0); ffma2(acc2[0][1], a.x, B1);
                    ffma2(acc2[0][2], a.x, B2); ffma2(acc2[0][NCOL - 1], a.x, B3);
                    ffma2(acc2[1][0], a.y, B0); ffma2(acc2[1][1], a.y, B1);
                    ffma2(acc2[1][2], a.y, B2); ffma2(acc2[1][NCOL - 1], a.y, B3);
                } else {
                    float2 w2 = *(const float2*)&w_s[k * NN + n0];
                    u64 B0 = dup2(w2.x), B1 = dup2(w2.y);
                    ffma2(acc2[0][0], a.x, B0); ffma2(acc2[0][NCOL - 1], a.x, B1);
                    ffma2(acc2[1][0], a.y, B0); ffma2(acc2[1][NCOL - 1], a.y, B1);
                }
            }
        }

        // ---- scatter gate pre-activations to g_s[nn][b] (padded stride 65) ----
#pragma unroll
        for (int p = 0; p < 2; p++)
#pragma unroll
            for (int j = 0; j < NCOL; j++) {
                float2 v = unpack2(acc2[p][j]);
                g_s[(n0 + j) * 65 + (m0 + 2 * p)]     = v.x;
                g_s[(n0 + j) * 65 + (m0 + 2 * p + 1)] = v.y;
            }
        __syncthreads();

        // ---- gate nonlinearity + state update (c in registers, fast gates) ----
#pragma unroll
        for (int r = 0; r < NR; r++) {
            int idx = tid + r * 128;
            int b  = idx & 63;
            int jj = idx >> 6;              // 0..JW-1
            float gi = g_s[(0 * JW + jj) * 65 + b];
            float gf = g_s[(1 * JW + jj) * 65 + b];
            float gg = g_s[(2 * JW + jj) * 65 + b];
            float go = g_s[(3 * JW + jj) * 65 + b];
            float cn = fsigmoid(gf) * c_reg[r] + fsigmoid(gi) * ftanh(gg);
            float hn = fsigmoid(go) * ftanh(cn);
            c_reg[r] = cn;
            // k-major h write: [dir][k][b], lanes on consecutive b -> coalesced
            hnext[(size_t)dir * HID * BATCH + (size_t)(jbase + jj) * BATCH + b] = hn;
            if (outp)   // row key time*64+b; not read until after this kernel ends
                outp[(size_t)(time * BATCH + b) * 1024 + dir * HID + jbase + jj] = hn;
        }

        // ---- grid barrier (gpu fence -> CCTL.IVALL; inter-block h visibility) ----
        __threadfence();
        __syncthreads();
        if (tid == 0) atomicAdd(&g_bar, 1);
        // hide next step's pre-activation DRAM latency under barrier skew
        // (pre is immutable during this kernel, so this is race-free)
        prefetch_pre(t + 1 < T_LEN ? t + 1 : t);
        if (tid == 0) {
            int target = (t + 1) * nb;
            while (ld_acquire_gpu(&g_bar) < target) { }
        }
        __syncthreads();
    }
}

// ---------------------------------------------------------------------------
// Layer-1 backward direction: only its FIRST step (at t=T-1) is ever observed
// by the head (out1[:, -1, 512:]), with zero initial state.
// One warp per (b, j). grid 4096 x 256 threads.
// ---------------------------------------------------------------------------
__global__ __launch_bounds__(256)
void lstm1_bwd_first_step_kernel(const float* __restrict__ wih,   // [2,2048,1024]
                                 const float* __restrict__ bih,   // [2,2048]
                                 const float* __restrict__ bhh)   // [2,2048]
{
    int gw   = blockIdx.x * 8 + (threadIdx.x >> 5);   // global warp
    int lane = threadIdx.x & 31;
    int b = gw >> 9;          // 0..63
    int j = gw & 511;         // 0..511
    // out0 rows keyed t*64+b
    const float* x = g_out0 + (size_t)((T_LEN - 1) * BATCH + b) * 1024;

    float g[4];
#pragma unroll
    for (int gate = 0; gate < 4; gate++) {
        const float* wr = wih + (size_t)(GATES + gate * HID + j) * L1_K;
        float s = 0.0f;
        for (int k = lane; k < L1_K; k += 32) s += x[k] * wr[k];
#pragma unroll
        for (int off = 16; off > 0; off >>= 1) s += __shfl_down_sync(0xffffffffu, s, off);
        g[gate] = s;
    }
    if (lane == 0) {
#pragma unroll
        for (int gate = 0; gate < 4; gate++)
            g[gate] += bih[GATES + gate * HID + j] + bhh[GATES + gate * HID + j];
        float cn = fsigmoid(g[0]) * ftanh(g[2]);      // f-gate * c0 = 0
        g_hbwd1[b][j] = fsigmoid(g[3]) * ftanh(cn);
    }
}

// ---------------------------------------------------------------------------
// Head: last = concat(h1_fwd_final, h1_bwd_step); LayerNorm; FC(1024->512)+ReLU;
// FC(512->1). One block per batch element.
// ---------------------------------------------------------------------------
__device__ __forceinline__ float block_reduce_sum(float v, float* red) {
    int tid = threadIdx.x;
    red[tid] = v;
    __syncthreads();
#pragma unroll
    for (int s = 128; s > 0; s >>= 1) {
        if (tid < s) red[tid] += red[tid + s];
        __syncthreads();
    }
    float r = red[0];
    __syncthreads();
    return r;
}

__global__ __launch_bounds__(256)
void head_kernel(const float* __restrict__ lng, const float* __restrict__ lnb,
                 const float* __restrict__ w1,  const float* __restrict__ b1,
                 const float* __restrict__ w2,  const float* __restrict__ b2,
                 float* __restrict__ out)
{
    __shared__ float yv[1024];
    __shared__ float zv[512];
    __shared__ float red[256];
    const int b = blockIdx.x;
    const int tid = threadIdx.x;

    // gather last timestep: fwd final h lives in parity plane 0 (T_LEN even);
    // g_h is k-major [parity][dir][k][b]
#pragma unroll
    for (int r = 0; r < 4; r++) {
        int k = tid + r * 256;
        yv[k] = (k < HID) ? g_h[0][0][k][b] : g_hbwd1[b][k - HID];
    }
    __syncthreads();

    float s = 0.0f;
#pragma unroll
    for (int r = 0; r < 4; r++) s += yv[tid + r * 256];
    float mu = block_reduce_sum(s, red) * (1.0f / 1024.0f);

    float s2 = 0.0f;
#pragma unroll
    for (int r = 0; r < 4; r++) {
        float d = yv[tid + r * 256] - mu;
        s2 += d * d;
    }
    float var = block_reduce_sum(s2, red) * (1.0f / 1024.0f);
    float inv = rsqrtf(var + 1e-5f);

#pragma unroll
    for (int r = 0; r < 4; r++) {
        int k = tid + r * 256;
        yv[k] = (yv[k] - mu) * inv * lng[k] + lnb[k];
    }
    __syncthreads();

    // FC1 + ReLU: 512 outputs, 2 per thread
#pragma unroll
    for (int r = 0; r < 2; r++) {
        int n = tid + r * 256;
        const float* wr = w1 + (size_t)n * 1024;
        float acc = 0.0f;
        for (int k = 0; k < 1024; k++) acc += yv[k] * wr[k];
        zv[n] = fmaxf(acc + b1[n], 0.0f);
    }
    __syncthreads();

    // FC2
    float a = 0.0f;
    for (int n = tid; n < 512; n += 256) a += zv[n] * w2[n];
    float total = block_reduce_sum(a, red);
    if (tid == 0) out[b] = total + b2[0];
}

// ---------------------------------------------------------------------------
// Launch
// ---------------------------------------------------------------------------
extern "C" void kernel_launch(void* const* d_in, const int* in_sizes, int n_in,
                              void* d_out, int out_size)
{
    const float* x    = (const float*)d_in[0];
    const float* wih0 = (const float*)d_in[1];
    const float* whh0 = (const float*)d_in[2];
    const float* bih0 = (const float*)d_in[3];
    const float* bhh0 = (const float*)d_in[4];
    const float* wih1 = (const float*)d_in[5];
    const float* whh1 = (const float*)d_in[6];
    const float* bih1 = (const float*)d_in[7];
    const float* bhh1 = (const float*)d_in[8];
    const float* lng  = (const float*)d_in[9];
    const float* lnb  = (const float*)d_in[10];
    const float* w1   = (const float*)d_in[11];
    const float* b1   = (const float*)d_in[12];
    const float* w2   = (const float*)d_in[13];
    const float* b2   = (const float*)d_in[14];
    float* out = (float*)d_out;

    float *pre0, *pre1, *out0, *hbuf;
    cudaGetSymbolAddress((void**)&pre0, g_pre0);
    cudaGetSymbolAddress((void**)&pre1, g_pre1);
    cudaGetSymbolAddress((void**)&out0, g_out0);
    cudaGetSymbolAddress((void**)&hbuf, g_h);

    cudaFuncSetAttribute(lstm_layer_persistent_kernel<8>,
                         cudaFuncAttributeMaxDynamicSharedMemorySize, StepCfg<8>::SMEM);
    cudaFuncSetAttribute(lstm_layer_persistent_kernel<4>,
                         cudaFuncAttributeMaxDynamicSharedMemorySize, StepCfg<4>::SMEM);

    const int ZERO_BLOCKS = (2 * 2 * BATCH * HID + 255) / 256;

    // ---- Layer 0: input projection. X rows are b*512+t (input layout); output
    //      rows permuted to t*64+b for streaming recurrence reads. ----
    gemm_bias_kernel<<<dim3(4096 / 128, M_ROWS / 128), 256>>>(
        x, wih0, bih0, bhh0, pre0, M_ROWS, 4096, L0_K, /*permute=*/1);

    // ---- Layer 0 recurrence: ONE persistent launch, 512 steps, fwd+bwd ----
    // JW=8: 64 j-tiles x 2 dirs = 128 blocks (single wave).
    zero_states_kernel<<<ZERO_BLOCKS, 256>>>();
    lstm_layer_persistent_kernel<8><<<dim3(64, 2), 128, StepCfg<8>::SMEM>>>(
        pre0, 4096, whh0, hbuf, out0);

    // ---- Layer 1 fwd: input projection. X = out0 rows already t*64+b, so
    //      output rows inherit the same key with no permutation. ----
    gemm_bias_kernel<<<dim3(2048 / 128, M_ROWS / 128), 256>>>(
        out0, wih1, bih1, bhh1, pre1, M_ROWS, 2048, L1_K, /*permute=*/0);

    // ---- Layer 1 fwd recurrence (only final h is consumed) ----
    // JW=4: 128 j-tiles x 1 dir = 128 blocks (full chip, single wave).
    zero_states_kernel<<<ZERO_BLOCKS, 256>>>();
    lstm_layer_persistent_kernel<4><<<dim3(128, 1), 128, StepCfg<4>::SMEM>>>(
        pre1, 2048, whh1, hbuf, nullptr);

    // ---- Layer 1 bwd: single observable step at t = T-1 ----
    lstm1_bwd_first_step_kernel<<<4096, 256>>>(wih1, bih1, bhh1);

    // ---- Head ----
    head_kernel<<<BATCH, 256>>>(lng, lnb, w1, b1, w2, b2, out);
}

// round 16
// speedup vs baseline: 1.0490x; 1.0490x over previous
#include <cuda_runtime.h>
#include <math.h>
#include <stdint.h>

// Problem constants
#define T_LEN 512
#define BATCH 64
#define HID   512
#define GATES 2048          // 4*H
#define L0_K  256
#define L1_K  1024
#define M_ROWS (BATCH * T_LEN)   // 32768

typedef unsigned long long u64;

// ---------------------------------------------------------------------------
// Packed f32x2 helpers (sm_100+; FFMA2 is only reachable via PTX)
// ---------------------------------------------------------------------------
__device__ __forceinline__ u64 dup2(float x) {
    u64 r; asm("mov.b64 %0, {%1, %1};" : "=l"(r) : "f"(x)); return r;
}
__device__ __forceinline__ void ffma2(u64& d, u64 a, u64 b) {
    asm("fma.rn.f32x2 %0, %1, %2, %0;" : "+l"(d) : "l"(a), "l"(b));
}
__device__ __forceinline__ u64 pack2(float lo, float hi) {
    u64 r; asm("mov.b64 %0, {%1, %2};" : "=l"(r) : "f"(lo), "f"(hi)); return r;
}
__device__ __forceinline__ float2 unpack2(u64 v) {
    float2 r; asm("mov.b64 {%0, %1}, %2;" : "=f"(r.x), "=f"(r.y) : "l"(v)); return r;
}

// cp.async: 16B global->shared, L2-direct (.cg). Per-thread commit groups.
__device__ __forceinline__ void cp_async16(void* smem_ptr, const void* gptr) {
    uint32_t s = (uint32_t)__cvta_generic_to_shared(smem_ptr);
    asm volatile("cp.async.cg.shared.global [%0], [%1], 16;" :: "r"(s), "l"(gptr));
}
__device__ __forceinline__ void cp_async_commit() {
    asm volatile("cp.async.commit_group;");
}
template <int N>
__device__ __forceinline__ void cp_async_wait() {
    asm volatile("cp.async.wait_group %0;" :: "n"(N) : "memory");
}

// Fast gates: MUFU ex2-based exp (2-ulp). Avoid tanh.approx (abs err ~9e-4).
__device__ __forceinline__ float fsigmoid(float x) {
    return 1.0f / (1.0f + __expf(-x));
}
__device__ __forceinline__ float ftanh(float x) {
    return 2.0f / (1.0f + __expf(-2.0f * x)) - 1.0f;
}

// ---------------------------------------------------------------------------
// Scratch. Row key for pre0/pre1/out0 is (t*64 + b); g_h is K-MAJOR
// [parity][dir][k][b] so the per-step smem fill is a contiguous cp.async copy.
// ---------------------------------------------------------------------------
__device__ float g_pre0[(size_t)M_ROWS * 4096];
__device__ float g_pre1[(size_t)M_ROWS * 2048];
__device__ float g_out0[(size_t)M_ROWS * 1024];
__device__ float g_h[2][2][HID][BATCH];
__device__ float g_hbwd1[BATCH][HID];
__device__ int   g_bar;

__global__ void zero_states_kernel() {
    int i = blockIdx.x * blockDim.x + threadIdx.x;
    if (i == 0) g_bar = 0;
    if (i < 2 * 2 * BATCH * HID) ((float*)g_h)[i] = 0.0f;
}

// ---------------------------------------------------------------------------
// Input-projection GEMM. Measured R15: occ 12.5% (130 regs -> 1 CTA/SM),
// issue 27.3% -> latency/sync-bound. Fix: __launch_bounds__(256,2) caps regs
// at 128 so 2 CTAs co-reside and one block's load/sync phases overlap the
// other's FFMA2 window.
// ---------------------------------------------------------------------------
__global__ __launch_bounds__(256, 2)
void gemm_bias_kernel(const float* __restrict__ X, const float* __restrict__ W,
                      const float* __restrict__ bias1, const float* __restrict__ bias2,
                      float* __restrict__ Y, int M, int N, int K, int permute)
{
    __shared__ float Xs[16][128];
    __shared__ float Ws[16][128];

    const int tid   = threadIdx.x;
    const int mBase = blockIdx.y * 128;
    const int nBase = blockIdx.x * 128;
    const int tm = tid >> 4;
    const int tn = tid & 15;
    const int m0 = tm * 8;
    const int n0 = tn * 8;

    u64 acc2[4][8];
#pragma unroll
    for (int i = 0; i < 4; i++)
#pragma unroll
        for (int j = 0; j < 8; j++) acc2[i][j] = 0ull;

    int lrr[2], lkq[2];
#pragma unroll
    for (int q = 0; q < 2; q++) {
        int idx = tid + q * 256;
        lrr[q] = idx & 127;
        lkq[q] = idx >> 7;
    }

    float4 vx[2], vw[2];
#pragma unroll
    for (int q = 0; q < 2; q++) {
        vx[q] = *(const float4*)&X[(size_t)(mBase + lrr[q]) * K + 0 + lkq[q] * 4];
        vw[q] = *(const float4*)&W[(size_t)(nBase + lrr[q]) * K + 0 + lkq[q] * 4];
    }

    for (int kt = 0; kt < K; kt += 16) {
#pragma unroll
        for (int q = 0; q < 2; q++) {
            int rr = lrr[q], kq = lkq[q];
            Xs[kq * 4 + 0][rr] = vx[q].x; Xs[kq * 4 + 1][rr] = vx[q].y;
            Xs[kq * 4 + 2][rr] = vx[q].z; Xs[kq * 4 + 3][rr] = vx[q].w;
            Ws[kq * 4 + 0][rr] = vw[q].x; Ws[kq * 4 + 1][rr] = vw[q].y;
            Ws[kq * 4 + 2][rr] = vw[q].z; Ws[kq * 4 + 3][rr] = vw[q].w;
        }
        __syncthreads();

        if (kt + 16 < K) {
#pragma unroll
            for (int q = 0; q < 2; q++) {
                vx[q] = *(const float4*)&X[(size_t)(mBase + lrr[q]) * K + (kt + 16) + lkq[q] * 4];
                vw[q] = *(const float4*)&W[(size_t)(nBase + lrr[q]) * K + (kt + 16) + lkq[q] * 4];
            }
        }

#pragma unroll
        for (int kk = 0; kk < 16; kk++) {
            ulonglong2 a01 = *(const ulonglong2*)&Xs[kk][m0];
            ulonglong2 a23 = *(const ulonglong2*)&Xs[kk][m0 + 4];
            float4 b0 = *(const float4*)&Ws[kk][n0];
            float4 b1 = *(const float4*)&Ws[kk][n0 + 4];
            u64 A[4] = { a01.x, a01.y, a23.x, a23.y };
            u64 B[8] = { dup2(b0.x), dup2(b0.y), dup2(b0.z), dup2(b0.w),
                         dup2(b1.x), dup2(b1.y), dup2(b1.z), dup2(b1.w) };
#pragma unroll
            for (int i = 0; i < 4; i++)
#pragma unroll
                for (int j = 0; j < 8; j++) ffma2(acc2[i][j], A[i], B[j]);
        }
        __syncthreads();
    }

#pragma unroll
    for (int i = 0; i < 4; i++) {
        int mA = mBase + m0 + 2 * i;
        int mB = mA + 1;
        if (permute) {
            mA = (mA & (T_LEN - 1)) * BATCH + (mA >> 9);
            mB = (mB & (T_LEN - 1)) * BATCH + (mB >> 9);
        }
        size_t row0 = (size_t)mA * N;
        size_t row1 = (size_t)mB * N;
#pragma unroll
        for (int j = 0; j < 8; j++) {
            int col = nBase + n0 + j;
            float bsum = bias1[col] + bias2[col];
            float2 v = unpack2(acc2[i][j]);
            Y[row0 + col] = v.x + bsum;
            Y[row1 + col] = v.y + bsum;
        }
    }
}

// ---------------------------------------------------------------------------
// Persistent LSTM layer, REGISTER-GATE mapping: each thread owns all 4 gates
// of ONE j-column for MB batches, so the gate nonlinearity runs entirely in
// registers — no g_s scatter/gather, 3 fewer __syncthreads per step (4 total).
// w_s is laid out [k][jj][gate] so the 4 gate weights are one LDS.128.
// Per-k issues (JW=8): 1 LDS.128(h pair) + 1 LDS.128(w) + 4 dup2 + 8 FFMA2
// = 14 <= 16-cyc fma floor. h ping-pongs k-major via a 2-chunk cp.async
// pipeline overlapped with the GEMM. Grid <= 128 blocks @ 1 CTA/SM = single
// wave -> software grid barrier safe.
// ---------------------------------------------------------------------------
template <int JW>
struct StepCfg {
    static const int NN   = 4 * JW;                  // gate-cols per block
    static const int SMEM = (512 * 64 + 512 * NN) * 4;  // h_s + w_s (no g_s)
    static const int MB   = JW / 2;                  // batches per thread
    static const int NP   = MB / 2;                  // batch-pairs per thread
};

#define KCHUNK 256                                   // 2 chunks

__device__ __forceinline__ int ld_acquire_gpu(const int* p) {
    int v;
    asm volatile("ld.acquire.gpu.global.s32 %0, [%1];" : "=r"(v) : "l"(p) : "memory");
    return v;
}

template <int JW>
__global__ __launch_bounds__(128)
void lstm_layer_persistent_kernel(const float* __restrict__ pre, int preN,
                                  const float* __restrict__ whh,
                                  float* __restrict__ hbuf,    // [2][2][HID][BATCH]
                                  float* __restrict__ outp)    // rows t*64+b, or null
{
    const int NN = StepCfg<JW>::NN;
    const int MB = StepCfg<JW>::MB;
    const int NP = StepCfg<JW>::NP;

    extern __shared__ float sm[];
    float* h_s = sm;                        // [k][b]  512 x 64
    float* w_s = sm + 512 * 64;             // [k][jj*4+gate] 512 x NN

    const int tid   = threadIdx.x;
    const int dir   = blockIdx.y;
    const int jbase = blockIdx.x * JW;
    const int nb    = gridDim.x * gridDim.y;
    const int HPAR  = 2 * BATCH * HID;

    // ---- load w_hh slice ONCE, k-major, col index jj*4+gate ----
    {
        int nn = tid % NN;                  // source row id within slice
        int kg = tid / NN;
        int gate = nn / JW, jj = nn % JW;
        int col = jj * 4 + gate;            // [k][jj][gate] layout
        const float4* wsrc =
            (const float4*)(whh + (size_t)(dir * GATES + gate * HID + jbase + jj) * HID);
#pragma unroll 4
        for (int kq = kg * NN; kq < kg * NN + NN; kq++) {
            float4 v = wsrc[kq];
            int k = kq * 4;
            w_s[(k + 0) * NN + col] = v.x;
            w_s[(k + 1) * NN + col] = v.y;
            w_s[(k + 2) * NN + col] = v.z;
            w_s[(k + 3) * NN + col] = v.w;
        }
    }

    // thread tile: all 4 gates of column (jbase+jj) for MB batches
    const int jj = tid % JW;
    const int tm = tid / JW;                // 0..128/JW-1
    const int m0 = tm * MB;

    float c_reg[MB];
#pragma unroll
    for (int r = 0; r < MB; r++) c_reg[r] = 0.0f;

    // pre-activation prefetch: pf[i][g] for batch m0+i, gate g
    float pf[MB][4];
    auto prefetch_pre = [&](int tt) {
        int time2 = dir ? (T_LEN - 1 - tt) : tt;
#pragma unroll
        for (int i = 0; i < MB; i++) {
            size_t rowb = (size_t)(time2 * BATCH + m0 + i) * preN
                          + dir * GATES + jbase + jj;
#pragma unroll
            for (int g = 0; g < 4; g++)
                pf[i][g] = pre[rowb + g * HID];
        }
    };

    prefetch_pre(0);

    for (int t = 0; t < T_LEN; t++) {
        const float* hprev = hbuf + (size_t)(t & 1) * HPAR;
        float*       hnext = hbuf + (size_t)((t + 1) & 1) * HPAR;
        const int time = dir ? (T_LEN - 1 - t) : t;

        // acc2[p][g] packs batches (m0+2p, m0+2p+1), gate g
        u64 acc2[NP][4];
#pragma unroll
        for (int p = 0; p < NP; p++)
#pragma unroll
            for (int g = 0; g < 4; g++)
                acc2[p][g] = pack2(pf[2 * p][g], pf[2 * p + 1][g]);

        // ---- 2-chunk cp.async h copy, overlapped with GEMM ----
        const float* hplane = hprev + (size_t)dir * HID * BATCH;
        auto copy_chunk = [&](int c) {
            const float4* src = (const float4*)(hplane + c * KCHUNK * BATCH);
            float4*       dst = (float4*)(h_s + c * KCHUNK * BATCH);
#pragma unroll
            for (int i = 0; i < (KCHUNK * BATCH / 4) / 128; i++)
                cp_async16(dst + tid + i * 128, src + tid + i * 128);
            cp_async_commit();
        };

        copy_chunk(0);
        copy_chunk(1);

#pragma unroll
        for (int c = 0; c < HID / KCHUNK; c++) {
            if (c == 0) cp_async_wait<1>(); else cp_async_wait<0>();
            __syncthreads();                 // chunk c visible (t=0,c=0: + w_s)

#pragma unroll 4
            for (int k = c * KCHUNK; k < (c + 1) * KCHUNK; k++) {
                float4 w4 = *(const float4*)&w_s[k * NN + jj * 4];  // 4 gates
                u64 B0 = dup2(w4.x), B1 = dup2(w4.y), B2 = dup2(w4.z), B3 = dup2(w4.w);
                if (NP == 2) {
                    ulonglong2 a = *(const ulonglong2*)&h_s[k * 64 + m0];
                    ffma2(acc2[0][0], a.x, B0); ffma2(acc2[0][1], a.x, B1);
                    ffma2(acc2[0][2], a.x, B2); ffma2(acc2[0][3], a.x, B3);
                    ffma2(acc2[NP - 1][0], a.y, B0); ffma2(acc2[NP - 1][1], a.y, B1);
                    ffma2(acc2[NP - 1][2], a.y, B2); ffma2(acc2[NP - 1][3], a.y, B3);
                } else {
                    u64 a = *(const u64*)&h_s[k * 64 + m0];
                    ffma2(acc2[0][0], a, B0); ffma2(acc2[0][1], a, B1);
                    ffma2(acc2[0][2], a, B2); ffma2(acc2[0][3], a, B3);
                }
            }
        }

        // ---- gates entirely in registers ----
        float hn_v[MB];
#pragma unroll
        for (int p = 0; p < NP; p++) {
            float2 gi = unpack2(acc2[p][0]);
            float2 gf = unpack2(acc2[p][1]);
            float2 gg = unpack2(acc2[p][2]);
            float2 go = unpack2(acc2[p][3]);
            {
                int r = 2 * p;
                float cn = fsigmoid(gf.x) * c_reg[r] + fsigmoid(gi.x) * ftanh(gg.x);
                hn_v[r] = fsigmoid(go.x) * ftanh(cn);
                c_reg[r] = cn;
            }
            {
                int r = 2 * p + 1;
                float cn = fsigmoid(gf.y) * c_reg[r] + fsigmoid(gi.y) * ftanh(gg.y);
                hn_v[r] = fsigmoid(go.y) * ftanh(cn);
                c_reg[r] = cn;
            }
        }

        // h write: [dir][k=jbase+jj][b=m0..m0+MB-1] -> one vector store
        {
            float* hd = hnext + (size_t)dir * HID * BATCH
                        + (size_t)(jbase + jj) * BATCH + m0;
            if (MB == 4) *(float4*)hd = make_float4(hn_v[0], hn_v[1], hn_v[2], hn_v[MB - 1]);
            else         *(float2*)hd = make_float2(hn_v[0], hn_v[MB - 1]);
        }
        if (outp) {
#pragma unroll
            for (int i = 0; i < MB; i++)
                outp[(size_t)(time * BATCH + m0 + i) * 1024 + dir * HID + jbase + jj] = hn_v[i];
        }

        // ---- grid barrier (gpu fence; prefetch hides pre-read latency) ----
        __threadfence();
        __syncthreads();
        if (tid == 0) atomicAdd(&g_bar, 1);
        prefetch_pre(t + 1 < T_LEN ? t + 1 : t);
        if (tid == 0) {
            int target = (t + 1) * nb;
            while (ld_acquire_gpu(&g_bar) < target) { }
        }
        __syncthreads();
    }
}

// ---------------------------------------------------------------------------
// Layer-1 backward: only its first step (t=T-1, zero state) is observed.
// ---------------------------------------------------------------------------
__global__ __launch_bounds__(256)
void lstm1_bwd_first_step_kernel(const float* __restrict__ wih,
                                 const float* __restrict__ bih,
                                 const float* __restrict__ bhh)
{
    int gw   = blockIdx.x * 8 + (threadIdx.x >> 5);
    int lane = threadIdx.x & 31;
    int b = gw >> 9;
    int j = gw & 511;
    const float* x = g_out0 + (size_t)((T_LEN - 1) * BATCH + b) * 1024;

    float g[4];
#pragma unroll
    for (int gate = 0; gate < 4; gate++) {
        const float* wr = wih + (size_t)(GATES + gate * HID + j) * L1_K;
        float s = 0.0f;
        for (int k = lane; k < L1_K; k += 32) s += x[k] * wr[k];
#pragma unroll
        for (int off = 16; off > 0; off >>= 1) s += __shfl_down_sync(0xffffffffu, s, off);
        g[gate] = s;
    }
    if (lane == 0) {
#pragma unroll
        for (int gate = 0; gate < 4; gate++)
            g[gate] += bih[GATES + gate * HID + j] + bhh[GATES + gate * HID + j];
        float cn = fsigmoid(g[0]) * ftanh(g[2]);
        g_hbwd1[b][j] = fsigmoid(g[3]) * ftanh(cn);
    }
}

// ---------------------------------------------------------------------------
// Head
// ---------------------------------------------------------------------------
__device__ __forceinline__ float block_reduce_sum(float v, float* red) {
    int tid = threadIdx.x;
    red[tid] = v;
    __syncthreads();
#pragma unroll
    for (int s = 128; s > 0; s >>= 1) {
        if (tid < s) red[tid] += red[tid + s];
        __syncthreads();
    }
    float r = red[0];
    __syncthreads();
    return r;
}

__global__ __launch_bounds__(256)
void head_kernel(const float* __restrict__ lng, const float* __restrict__ lnb,
                 const float* __restrict__ w1,  const float* __restrict__ b1,
                 const float* __restrict__ w2,  const float* __restrict__ b2,
                 float* __restrict__ out)
{
    __shared__ float yv[1024];
    __shared__ float zv[512];
    __shared__ float red[256];
    const int b = blockIdx.x;
    const int tid = threadIdx.x;

#pragma unroll
    for (int r = 0; r < 4; r++) {
        int k = tid + r * 256;
        yv[k] = (k < HID) ? g_h[0][0][k][b] : g_hbwd1[b][k - HID];
    }
    __syncthreads();

    float s = 0.0f;
#pragma unroll
    for (int r = 0; r < 4; r++) s += yv[tid + r * 256];
    float mu = block_reduce_sum(s, red) * (1.0f / 1024.0f);

    float s2 = 0.0f;
#pragma unroll
    for (int r = 0; r < 4; r++) {
        float d = yv[tid + r * 256] - mu;
        s2 += d * d;
    }
    float var = block_reduce_sum(s2, red) * (1.0f / 1024.0f);
    float inv = rsqrtf(var + 1e-5f);

#pragma unroll
    for (int r = 0; r < 4; r++) {
        int k = tid + r * 256;
        yv[k] = (yv[k] - mu) * inv * lng[k] + lnb[k];
    }
    __syncthreads();

#pragma unroll
    for (int r = 0; r < 2; r++) {
        int n = tid + r * 256;
        const float* wr = w1 + (size_t)n * 1024;
        float acc = 0.0f;
        for (int k = 0; k < 1024; k++) acc += yv[k] * wr[k];
        zv[n] = fmaxf(acc + b1[n], 0.0f);
    }
    __syncthreads();

    float a = 0.0f;
    for (int n = tid; n < 512; n += 256) a += zv[n] * w2[n];
    float total = block_reduce_sum(a, red);
    if (tid == 0) out[b] = total + b2[0];
}

// ---------------------------------------------------------------------------
// Launch
// ---------------------------------------------------------------------------
extern "C" void kernel_launch(void* const* d_in, const int* in_sizes, int n_in,
                              void* d_out, int out_size)
{
    const float* x    = (const float*)d_in[0];
    const float* wih0 = (const float*)d_in[1];
    const float* whh0 = (const float*)d_in[2];
    const float* bih0 = (const float*)d_in[3];
    const float* bhh0 = (const float*)d_in[4];
    const float* wih1 = (const float*)d_in[5];
    const float* whh1 = (const float*)d_in[6];
    const float* bih1 = (const float*)d_in[7];
    const float* bhh1 = (const float*)d_in[8];
    const float* lng  = (const float*)d_in[9];
    const float* lnb  = (const float*)d_in[10];
    const float* w1   = (const float*)d_in[11];
    const float* b1   = (const float*)d_in[12];
    const float* w2   = (const float*)d_in[13];
    const float* b2   = (const float*)d_in[14];
    float* out = (float*)d_out;

    float *pre0, *pre1, *out0, *hbuf;
    cudaGetSymbolAddress((void**)&pre0, g_pre0);
    cudaGetSymbolAddress((void**)&pre1, g_pre1);
    cudaGetSymbolAddress((void**)&out0, g_out0);
    cudaGetSymbolAddress((void**)&hbuf, g_h);

    cudaFuncSetAttribute(lstm_layer_persistent_kernel<8>,
                         cudaFuncAttributeMaxDynamicSharedMemorySize, StepCfg<8>::SMEM);
    cudaFuncSetAttribute(lstm_layer_persistent_kernel<4>,
                         cudaFuncAttributeMaxDynamicSharedMemorySize, StepCfg<4>::SMEM);

    const int ZERO_BLOCKS = (2 * 2 * BATCH * HID + 255) / 256;

    // Layer 0 input projection (rows permuted to t*64+b)
    gemm_bias_kernel<<<dim3(4096 / 128, M_ROWS / 128), 256>>>(
        x, wih0, bih0, bhh0, pre0, M_ROWS, 4096, L0_K, /*permute=*/1);

    // Layer 0 recurrence: JW=8, 64 j-tiles x 2 dirs = 128 blocks, single wave
    zero_states_kernel<<<ZERO_BLOCKS, 256>>>();
    lstm_layer_persistent_kernel<8><<<dim3(64, 2), 128, StepCfg<8>::SMEM>>>(
        pre0, 4096, whh0, hbuf, out0);

    // Layer 1 fwd input projection (rows already t*64+b)
    gemm_bias_kernel<<<dim3(2048 / 128, M_ROWS / 128), 256>>>(
        out0, wih1, bih1, bhh1, pre1, M_ROWS, 2048, L1_K, /*permute=*/0);

    // Layer 1 fwd recurrence: JW=4, 128 blocks, single wave
    zero_states_kernel<<<ZERO_BLOCKS, 256>>>();
    lstm_layer_persistent_kernel<4><<<dim3(128, 1), 128, StepCfg<4>::SMEM>>>(
        pre1, 2048, whh1, hbuf, nullptr);

    // Layer 1 bwd: single observable step
    lstm1_bwd_first_step_kernel<<<4096, 256>>>(wih1, bih1, bhh1);

    // Head
    head_kernel<<<BATCH, 256>>>(lng, lnb, w1, b1, w2, b2, out);
}